// round 2
// baseline (speedup 1.0000x reference)
#include <cuda_runtime.h>
#include <cuda_bf16.h>
#include <math_constants.h>

// Problem constants
#define NN   50000      // nodes
#define EE   200000     // edges per relation
#define RR   4          // relations
#define CC   128        // feature dim (all layers: IN = H*HID = H*OUT input = 128)
#define HH   4          // heads
#define DD   32         // per-head dim

// ---------------------------------------------------------------------------
// Device scratch (allocation-free rule: __device__ globals)
// ---------------------------------------------------------------------------
__device__ float g_fs[RR * NN * CC];     // per-relation src-transformed features
__device__ float g_fd[RR * NN * CC];     // per-relation dst-transformed features
__device__ float g_h1[NN * CC];          // layer0 output
__device__ float g_h2[NN * CC];          // layer1 output
__device__ int   g_cnt[RR * NN];         // degree counts / fill cursors
__device__ int   g_off[RR * (NN + 1)];   // CSR offsets (per relation, local [0,E))
__device__ int   g_src[RR * EE];         // CSR src lists sorted by dst

// ---------------------------------------------------------------------------
// CSR construction
// ---------------------------------------------------------------------------
__global__ void k_zero_cnt(int* cnt) {
    int i = blockIdx.x * blockDim.x + threadIdx.x;
    if (i < RR * NN) cnt[i] = 0;
}

__global__ void k_count(const int* __restrict__ edst, int* cnt) {
    int i = blockIdx.x * blockDim.x + threadIdx.x;
    if (i >= RR * EE) return;
    int r = i / EE;
    int dst = edst[i];
    atomicAdd(&cnt[r * NN + dst], 1);
}

// one block per relation: chunked Hillis-Steele scan of 50000 counts
__global__ void k_scan(const int* __restrict__ cnt, int* off) {
    int r = blockIdx.x;
    int t = threadIdx.x;
    const int CH = (NN + 1023) / 1024;   // 49
    __shared__ int sums[1024];
    int base = t * CH;
    int s = 0;
    for (int i = 0; i < CH; i++) {
        int idx = base + i;
        if (idx < NN) s += cnt[r * NN + idx];
    }
    sums[t] = s;
    __syncthreads();
    for (int o = 1; o < 1024; o <<= 1) {
        int v = (t >= o) ? sums[t - o] : 0;
        __syncthreads();
        sums[t] += v;
        __syncthreads();
    }
    int run = (t == 0) ? 0 : sums[t - 1];   // exclusive prefix for this chunk
    for (int i = 0; i < CH; i++) {
        int idx = base + i;
        if (idx < NN) {
            off[r * (NN + 1) + idx] = run;
            run += cnt[r * NN + idx];
        }
    }
    if (t == 1023) off[r * (NN + 1) + NN] = run;   // == EE
}

__global__ void k_copy_cursor(const int* __restrict__ off, int* cur) {
    int i = blockIdx.x * blockDim.x + threadIdx.x;
    if (i >= RR * NN) return;
    int r = i / NN, n = i - r * NN;
    cur[i] = off[r * (NN + 1) + n];
}

__global__ void k_fill(const int* __restrict__ esrc, const int* __restrict__ edst,
                       int* cur, int* csr_src) {
    int i = blockIdx.x * blockDim.x + threadIdx.x;
    if (i >= RR * EE) return;
    int r = i / EE;
    int dst = edst[i];
    int pos = atomicAdd(&cur[r * NN + dst], 1);
    csr_src[r * EE + pos] = esrc[i];
}

// ---------------------------------------------------------------------------
// SGEMM: C[M,128] = A[M,128] @ W[128,128] + bias   (fp32, BM=128 BN=128 BK=16)
// 256 threads, 8x8 micro-tile per thread
// ---------------------------------------------------------------------------
__global__ __launch_bounds__(256) void k_sgemm128(
    const float* __restrict__ A, const float* __restrict__ W,
    const float* __restrict__ bias, float* __restrict__ C) {
    __shared__ float As[16][128];
    __shared__ float Bs[16][128];
    int tid = threadIdx.x;
    int ty = tid >> 4, tx = tid & 15;
    int m0 = blockIdx.x * 128;
    float acc[8][8] = {};

    for (int k0 = 0; k0 < 128; k0 += 16) {
        // A tile: 128 rows x 16 k, stored transposed As[k][m]
        {
            int row = tid >> 2;
            int c4  = (tid & 3) * 4;
            #pragma unroll
            for (int rr = 0; rr < 2; rr++) {
                int r_ = row + rr * 64;
                int g  = m0 + r_;
                float4 v = (g < NN) ? *(const float4*)(A + (size_t)g * CC + k0 + c4)
                                    : make_float4(0.f, 0.f, 0.f, 0.f);
                As[c4 + 0][r_] = v.x; As[c4 + 1][r_] = v.y;
                As[c4 + 2][r_] = v.z; As[c4 + 3][r_] = v.w;
            }
        }
        // B tile: 16 k x 128 n
        {
            int kk = tid >> 5;
            int n4 = (tid & 31) * 4;
            #pragma unroll
            for (int rr = 0; rr < 2; rr++) {
                int k_ = kk + rr * 8;
                *(float4*)&Bs[k_][n4] = *(const float4*)(W + (size_t)(k0 + k_) * 128 + n4);
            }
        }
        __syncthreads();
        #pragma unroll
        for (int kk = 0; kk < 16; kk++) {
            float a[8], b[8];
            #pragma unroll
            for (int i = 0; i < 8; i++) a[i] = As[kk][ty * 8 + i];
            #pragma unroll
            for (int j = 0; j < 8; j++) b[j] = Bs[kk][tx * 8 + j];
            #pragma unroll
            for (int i = 0; i < 8; i++)
                #pragma unroll
                for (int j = 0; j < 8; j++)
                    acc[i][j] = fmaf(a[i], b[j], acc[i][j]);
        }
        __syncthreads();
    }

    #pragma unroll
    for (int i = 0; i < 8; i++) {
        int m = m0 + ty * 8 + i;
        if (m >= NN) continue;
        #pragma unroll
        for (int j = 0; j < 8; j += 4) {
            int n = tx * 8 + j;
            float4 v;
            v.x = acc[i][j + 0] + bias[n + 0];
            v.y = acc[i][j + 1] + bias[n + 1];
            v.z = acc[i][j + 2] + bias[n + 2];
            v.w = acc[i][j + 3] + bias[n + 3];
            *(float4*)(C + (size_t)m * CC + n) = v;
        }
    }
}

// ---------------------------------------------------------------------------
// Edge aggregation: one warp per (dst, head); loops relations; online softmax.
// lane = per-head feature dim (DD=32). No atomics for the flatten path.
// MEAN: last layer, mean over heads via 0.25*atomicAdd into zeroed output.
// ---------------------------------------------------------------------------
template <bool MEAN>
__global__ __launch_bounds__(256) void k_edge_agg(
    const float* __restrict__ fs, const float* __restrict__ fd,
    const float* __restrict__ attn,     // [R,H,32]
    const int* __restrict__ off, const int* __restrict__ csr_src,
    float* __restrict__ out) {
    int wid  = (blockIdx.x * blockDim.x + threadIdx.x) >> 5;
    int lane = threadIdx.x & 31;
    int dst  = wid >> 2;        // HH = 4
    int h    = wid & 3;
    if (dst >= NN) return;

    float total = 0.f;
    #pragma unroll
    for (int r = 0; r < RR; r++) {
        const float* fsr = fs + (size_t)r * NN * CC;
        float fdv = fd[(size_t)r * NN * CC + (size_t)dst * CC + h * DD + lane];
        float av  = attn[r * HH * DD + h * DD + lane];
        int beg = off[r * (NN + 1) + dst];
        int end = off[r * (NN + 1) + dst + 1];

        float m = -CUDART_INF_F, den = 0.f, acc = 0.f;
        for (int e = beg; e < end; e++) {
            int src = csr_src[r * EE + e];
            float f = fsr[(size_t)src * CC + h * DD + lane];
            float x = f + fdv;
            float lr = (x > 0.f) ? x : 0.2f * x;       // leaky_relu(.,0.2)
            float p = lr * av;
            #pragma unroll
            for (int o = 16; o; o >>= 1)
                p += __shfl_xor_sync(0xFFFFFFFFu, p, o);
            float s = p;                                // identical on all lanes
            if (s > m) {
                float c = __expf(m - s);                // exp(-inf)=0 first iter
                den *= c; acc *= c; m = s;
            }
            float w = __expf(s - m);
            den += w;
            acc += w * f;
        }
        if (den > 0.f) total += acc / den;
    }

    if (MEAN) {
        atomicAdd(out + (size_t)dst * DD + lane, 0.25f * total);
    } else {
        out[(size_t)dst * CC + h * DD + lane] = total;
    }
}

// ---------------------------------------------------------------------------
// Launch
// ---------------------------------------------------------------------------
extern "C" void kernel_launch(void* const* d_in, const int* in_sizes, int n_in,
                              void* d_out, int out_size) {
    const float* x    = (const float*)d_in[0];
    const int*   esrc = (const int*)d_in[1];
    const int*   edst = (const int*)d_in[2];
    // layer l weights at d_in[3 + 5*l + {0..4}] = Wsrc, bsrc, Wdst, bdst, attn
    const float* Wsrc[3], *bsrc[3], *Wdst[3], *bdst[3], *attn[3];
    for (int l = 0; l < 3; l++) {
        Wsrc[l] = (const float*)d_in[3 + 5 * l + 0];
        bsrc[l] = (const float*)d_in[3 + 5 * l + 1];
        Wdst[l] = (const float*)d_in[3 + 5 * l + 2];
        bdst[l] = (const float*)d_in[3 + 5 * l + 3];
        attn[l] = (const float*)d_in[3 + 5 * l + 4];
    }

    void *p_fs, *p_fd, *p_h1, *p_h2, *p_cnt, *p_off, *p_src;
    cudaGetSymbolAddress(&p_fs,  g_fs);
    cudaGetSymbolAddress(&p_fd,  g_fd);
    cudaGetSymbolAddress(&p_h1,  g_h1);
    cudaGetSymbolAddress(&p_h2,  g_h2);
    cudaGetSymbolAddress(&p_cnt, g_cnt);
    cudaGetSymbolAddress(&p_off, g_off);
    cudaGetSymbolAddress(&p_src, g_src);
    float* fs = (float*)p_fs;  float* fd = (float*)p_fd;
    float* h1 = (float*)p_h1;  float* h2 = (float*)p_h2;
    int* cnt = (int*)p_cnt;    int* off = (int*)p_off;   int* csr_src = (int*)p_src;

    // --- CSR build (dst-sorted adjacency per relation) ---
    k_zero_cnt<<<(RR * NN + 255) / 256, 256>>>(cnt);
    k_count<<<(RR * EE + 255) / 256, 256>>>(edst, cnt);
    k_scan<<<RR, 1024>>>(cnt, off);
    k_copy_cursor<<<(RR * NN + 255) / 256, 256>>>(off, cnt);   // cnt now = cursors
    k_fill<<<(RR * EE + 255) / 256, 256>>>(esrc, edst, cnt, csr_src);

    const int GEMM_BLOCKS = (NN + 127) / 128;   // 391
    const int EDGE_BLOCKS = (NN * HH * 32 + 255) / 256;

    const float* h = x;
    for (int l = 0; l < 3; l++) {
        // 8 GEMMs: fs[r] = h@Wsrc[l][r]+bsrc, fd[r] = h@Wdst[l][r]+bdst
        for (int r = 0; r < RR; r++) {
            k_sgemm128<<<GEMM_BLOCKS, 256>>>(
                h, Wsrc[l] + (size_t)r * CC * CC, bsrc[l] + r * CC,
                fs + (size_t)r * NN * CC);
            k_sgemm128<<<GEMM_BLOCKS, 256>>>(
                h, Wdst[l] + (size_t)r * CC * CC, bdst[l] + r * CC,
                fd + (size_t)r * NN * CC);
        }
        if (l < 2) {
            float* hn = (l == 0) ? h1 : h2;
            k_edge_agg<false><<<EDGE_BLOCKS, 256>>>(fs, fd, attn[l], off, csr_src, hn);
            h = hn;
        } else {
            cudaMemsetAsync(d_out, 0, (size_t)out_size * sizeof(float), 0);
            k_edge_agg<true><<<EDGE_BLOCKS, 256>>>(fs, fd, attn[l], off, csr_src,
                                                   (float*)d_out);
        }
    }
}

// round 6
// speedup vs baseline: 1.6023x; 1.6023x over previous
#include <cuda_runtime.h>
#include <cuda_bf16.h>
#include <math_constants.h>
#include <cstdint>

// Problem constants
#define NN   50000
#define EE   200000
#define RR   4
#define CC   128
#define HH   4
#define DD   32

// ---------------------------------------------------------------------------
// Device scratch (allocation-free rule: __device__ globals)
// ---------------------------------------------------------------------------
__device__ float g_fs[RR * NN * CC];
__device__ float g_fd[RR * NN * CC];
__device__ float g_h1[NN * CC];
__device__ float g_h2[NN * CC];
__device__ int   g_cnt[RR * NN];
__device__ int   g_off[RR * (NN + 1)];
__device__ int   g_src[RR * EE];
__device__ __nv_bfloat16 g_ahi[NN * CC];
__device__ __nv_bfloat16 g_alo[NN * CC];
__device__ __nv_bfloat16 g_whi[3 * 8 * CC * CC];   // [layer][block(8)][n][k]
__device__ __nv_bfloat16 g_wlo[3 * 8 * CC * CC];
__device__ float         g_bias[3 * 8 * CC];

// ---------------------------------------------------------------------------
// CSR construction
// ---------------------------------------------------------------------------
__global__ void k_zero_cnt(int* cnt) {
    int i = blockIdx.x * blockDim.x + threadIdx.x;
    if (i < RR * NN) cnt[i] = 0;
}
__global__ void k_count(const int* __restrict__ edst, int* cnt) {
    int i = blockIdx.x * blockDim.x + threadIdx.x;
    if (i >= RR * EE) return;
    int r = i / EE;
    atomicAdd(&cnt[r * NN + edst[i]], 1);
}
__global__ void k_scan(const int* __restrict__ cnt, int* off) {
    int r = blockIdx.x;
    int t = threadIdx.x;
    const int CH = (NN + 1023) / 1024;
    __shared__ int sums[1024];
    int base = t * CH, s = 0;
    for (int i = 0; i < CH; i++) { int idx = base + i; if (idx < NN) s += cnt[r * NN + idx]; }
    sums[t] = s;
    __syncthreads();
    for (int o = 1; o < 1024; o <<= 1) {
        int v = (t >= o) ? sums[t - o] : 0;
        __syncthreads();
        sums[t] += v;
        __syncthreads();
    }
    int run = (t == 0) ? 0 : sums[t - 1];
    for (int i = 0; i < CH; i++) {
        int idx = base + i;
        if (idx < NN) { off[r * (NN + 1) + idx] = run; run += cnt[r * NN + idx]; }
    }
    if (t == 1023) off[r * (NN + 1) + NN] = run;
}
__global__ void k_copy_cursor(const int* __restrict__ off, int* cur) {
    int i = blockIdx.x * blockDim.x + threadIdx.x;
    if (i >= RR * NN) return;
    int r = i / NN, n = i - r * NN;
    cur[i] = off[r * (NN + 1) + n];
}
__global__ void k_fill(const int* __restrict__ esrc, const int* __restrict__ edst,
                       int* cur, int* csr_src) {
    int i = blockIdx.x * blockDim.x + threadIdx.x;
    if (i >= RR * EE) return;
    int r = i / EE;
    int pos = atomicAdd(&cur[r * NN + edst[i]], 1);
    csr_src[r * EE + pos] = esrc[i];
}

// ---------------------------------------------------------------------------
// fp32 -> bf16 hi/lo split conversions
// ---------------------------------------------------------------------------
__global__ void k_cvt_x(const float* __restrict__ x,
                        __nv_bfloat16* __restrict__ hi, __nv_bfloat16* __restrict__ lo) {
    int i = blockIdx.x * blockDim.x + threadIdx.x;
    if (i >= NN * CC / 4) return;
    float4 v = ((const float4*)x)[i];
    __nv_bfloat16 h0 = __float2bfloat16(v.x), h1 = __float2bfloat16(v.y);
    __nv_bfloat16 h2 = __float2bfloat16(v.z), h3 = __float2bfloat16(v.w);
    __nv_bfloat16 l0 = __float2bfloat16(v.x - __bfloat162float(h0));
    __nv_bfloat16 l1 = __float2bfloat16(v.y - __bfloat162float(h1));
    __nv_bfloat16 l2 = __float2bfloat16(v.z - __bfloat162float(h2));
    __nv_bfloat16 l3 = __float2bfloat16(v.w - __bfloat162float(h3));
    __nv_bfloat162 hp0(h0, h1), hp1(h2, h3), lp0(l0, l1), lp1(l2, l3);
    ((__nv_bfloat162*)hi)[2 * i]     = hp0;
    ((__nv_bfloat162*)hi)[2 * i + 1] = hp1;
    ((__nv_bfloat162*)lo)[2 * i]     = lp0;
    ((__nv_bfloat162*)lo)[2 * i + 1] = lp1;
}

// transpose W[r][k][n] -> out[r][n][k] with hi/lo split; also copy bias
__global__ void k_cvt_w(const float* __restrict__ W, const float* __restrict__ bvec,
                        __nv_bfloat16* __restrict__ w_hi, __nv_bfloat16* __restrict__ w_lo,
                        float* __restrict__ bias_out) {
    int i = blockIdx.x * blockDim.x + threadIdx.x;
    if (i >= RR * CC * CC) return;
    int r   = i / (CC * CC);
    int rem = i - r * (CC * CC);
    int n   = rem / CC;
    int k   = rem - n * CC;
    float w = W[(size_t)r * CC * CC + (size_t)k * CC + n];
    __nv_bfloat16 h = __float2bfloat16(w);
    __nv_bfloat16 l = __float2bfloat16(w - __bfloat162float(h));
    w_hi[i] = h;
    w_lo[i] = l;
    if (k == 0) bias_out[r * CC + n] = bvec[r * CC + n];
}

// ---------------------------------------------------------------------------
// HMMA helpers (portable mma.sync path — tcgen05 unavailable on compute_103)
// ---------------------------------------------------------------------------
__device__ __forceinline__ uint32_t smem_u32(const void* p) {
    uint32_t a;
    asm("{ .reg .u64 t; cvta.to.shared.u64 t, %1; cvt.u32.u64 %0, t; }"
        : "=r"(a) : "l"(p));
    return a;
}
__device__ __forceinline__ void ldsm_x4(uint32_t* r, uint32_t addr) {
    asm volatile("ldmatrix.sync.aligned.m8n8.x4.shared.b16 {%0,%1,%2,%3}, [%4];"
        : "=r"(r[0]), "=r"(r[1]), "=r"(r[2]), "=r"(r[3]) : "r"(addr));
}
#define MMA16816(c, a, b) \
    asm volatile("mma.sync.aligned.m16n8k16.row.col.f32.bf16.bf16.f32 " \
        "{%0,%1,%2,%3}, {%4,%5,%6,%7}, {%8,%9}, {%0,%1,%2,%3};" \
        : "+f"((c)[0]), "+f"((c)[1]), "+f"((c)[2]), "+f"((c)[3]) \
        : "r"((a)[0]), "r"((a)[1]), "r"((a)[2]), "r"((a)[3]), \
          "r"((b)[0]), "r"((b)[1]))

// SMEM tile geometry: [128 rows][64 k-chunk + 8 pad] bf16 (stride 72 elems =
// 144B = 36 words; 8 consecutive rows hit distinct 4-bank groups -> ldmatrix
// and the uint4 fill are both conflict-free).
#define TPAD       72
#define TILE_ELEMS (128 * TPAD)
#define GEMM_SMEM  (4 * TILE_ELEMS * 2)   // 73728 B: Ahi, Alo, Bhi, Blo

// ---------------------------------------------------------------------------
// bf16 hi/lo split GEMM via mma.sync.
// C[128m x 128n] = A[128x128] @ W_b[128x128], W stored [n][k].
// 3-term split: Ahi*Bhi + Ahi*Blo + Alo*Bhi, fp32 accumulate.
// grid = (391 M-tiles, 8 N-blocks). b<4 -> fs[r=b], else fd[r=b-4].
// 8 warps, warp tile 32(M) x 64(N).
// ---------------------------------------------------------------------------
__global__ __launch_bounds__(256) void k_gemm_mma(
    const __nv_bfloat16* __restrict__ a_hi, const __nv_bfloat16* __restrict__ a_lo,
    const __nv_bfloat16* __restrict__ w_hi, const __nv_bfloat16* __restrict__ w_lo,
    const float* __restrict__ bias,
    float* __restrict__ fs, float* __restrict__ fd) {
    extern __shared__ __align__(16) char dsm[];
    __nv_bfloat16* sAhi = (__nv_bfloat16*)dsm;
    __nv_bfloat16* sAlo = sAhi + TILE_ELEMS;
    __nv_bfloat16* sBhi = sAlo + TILE_ELEMS;
    __nv_bfloat16* sBlo = sBhi + TILE_ELEMS;

    const int tid  = threadIdx.x;
    const int wid  = tid >> 5;
    const int lane = tid & 31;
    const int wm   = wid >> 1;        // 0..3 : warp M index (32 rows each)
    const int wn   = wid & 1;         // 0..1 : warp N index (64 cols each)
    const int m0   = blockIdx.x * 128;
    const int b    = blockIdx.y;

    const __nv_bfloat16* gAhi = a_hi + (size_t)m0 * CC;
    const __nv_bfloat16* gAlo = a_lo + (size_t)m0 * CC;
    const __nv_bfloat16* gBhi = w_hi + (size_t)b * CC * CC;
    const __nv_bfloat16* gBlo = w_lo + (size_t)b * CC * CC;

    float acc[2][8][4];
    #pragma unroll
    for (int i = 0; i < 2; i++)
        #pragma unroll
        for (int j = 0; j < 8; j++)
            #pragma unroll
            for (int q = 0; q < 4; q++) acc[i][j][q] = 0.f;

    const int sub = lane >> 3;        // 0..3 (ldmatrix sub-matrix)
    const int rin = lane & 7;

    #pragma unroll
    for (int k0 = 0; k0 < 128; k0 += 64) {
        // ---- load 4 tiles gmem -> smem (each: 128 rows x 64 bf16) ----
        #pragma unroll
        for (int i = 0; i < 4; i++) {
            int idx = tid + i * 256;              // 0..1023
            int row = idx >> 3, ch = idx & 7;     // 8 x 16B chunks per row
            size_t go = (size_t)row * CC + k0 + ch * 8;
            int so = row * TPAD + ch * 8;
            uint4 zv = make_uint4(0u, 0u, 0u, 0u);
            bool okA = (m0 + row) < NN;
            *(uint4*)(sAhi + so) = okA ? *(const uint4*)(gAhi + go) : zv;
            *(uint4*)(sAlo + so) = okA ? *(const uint4*)(gAlo + go) : zv;
            *(uint4*)(sBhi + so) = *(const uint4*)(gBhi + go);
            *(uint4*)(sBlo + so) = *(const uint4*)(gBlo + go);
        }
        __syncthreads();

        // ---- 4 k16-steps over this 64-wide chunk ----
        #pragma unroll
        for (int kk = 0; kk < 64; kk += 16) {
            uint32_t afh[2][4], afl[2][4], bfh[8][2], bfl[8][2];
            // A fragments: rows wm*32 + mt*16 + {0..15}
            #pragma unroll
            for (int mt = 0; mt < 2; mt++) {
                int ar = wm * 32 + mt * 16 + (sub & 1) * 8 + rin;
                int ac = kk + (sub >> 1) * 8;
                int off = ar * TPAD + ac;
                ldsm_x4(afh[mt], smem_u32(sAhi + off));
                ldsm_x4(afl[mt], smem_u32(sAlo + off));
            }
            // B fragments: each ldmatrix.x4 covers 2 n8-tiles
            #pragma unroll
            for (int nt2 = 0; nt2 < 4; nt2++) {
                int br = wn * 64 + nt2 * 16 + (sub >> 1) * 8 + rin;
                int bc = kk + (sub & 1) * 8;
                int off = br * TPAD + bc;
                uint32_t t[4];
                ldsm_x4(t, smem_u32(sBhi + off));
                bfh[nt2 * 2][0] = t[0]; bfh[nt2 * 2][1] = t[1];
                bfh[nt2 * 2 + 1][0] = t[2]; bfh[nt2 * 2 + 1][1] = t[3];
                ldsm_x4(t, smem_u32(sBlo + off));
                bfl[nt2 * 2][0] = t[0]; bfl[nt2 * 2][1] = t[1];
                bfl[nt2 * 2 + 1][0] = t[2]; bfl[nt2 * 2 + 1][1] = t[3];
            }
            // 3-term accumulation
            #pragma unroll
            for (int mt = 0; mt < 2; mt++)
                #pragma unroll
                for (int nt = 0; nt < 8; nt++) {
                    MMA16816(acc[mt][nt], afh[mt], bfh[nt]);
                    MMA16816(acc[mt][nt], afh[mt], bfl[nt]);
                    MMA16816(acc[mt][nt], afl[mt], bfh[nt]);
                }
        }
        __syncthreads();
    }

    // ---- epilogue: add bias, store fp32 ----
    float* outp = (b < 4) ? (fs + (size_t)b * NN * CC)
                          : (fd + (size_t)(b - 4) * NN * CC);
    const float* bv = bias + b * CC;
    const int qr = lane >> 2, qc = lane & 3;
    #pragma unroll
    for (int mt = 0; mt < 2; mt++) {
        int mA = m0 + wm * 32 + mt * 16 + qr;
        #pragma unroll
        for (int nt = 0; nt < 8; nt++) {
            int n = wn * 64 + nt * 8 + qc * 2;
            float b0 = bv[n], b1 = bv[n + 1];
            if (mA < NN) {
                float2 v0 = make_float2(acc[mt][nt][0] + b0, acc[mt][nt][1] + b1);
                *(float2*)(outp + (size_t)mA * CC + n) = v0;
            }
            if (mA + 8 < NN) {
                float2 v1 = make_float2(acc[mt][nt][2] + b0, acc[mt][nt][3] + b1);
                *(float2*)(outp + (size_t)(mA + 8) * CC + n) = v1;
            }
        }
    }
}

// ---------------------------------------------------------------------------
// Edge aggregation: one warp per (dst, head); loops relations; online softmax
// ---------------------------------------------------------------------------
template <bool MEAN>
__global__ __launch_bounds__(256) void k_edge_agg(
    const float* __restrict__ fs, const float* __restrict__ fd,
    const float* __restrict__ attn,
    const int* __restrict__ off, const int* __restrict__ csr_src,
    float* __restrict__ out) {
    int wid  = (blockIdx.x * blockDim.x + threadIdx.x) >> 5;
    int lane = threadIdx.x & 31;
    int dst  = wid >> 2;
    int h    = wid & 3;
    if (dst >= NN) return;

    float total = 0.f;
    #pragma unroll
    for (int r = 0; r < RR; r++) {
        const float* fsr = fs + (size_t)r * NN * CC;
        float fdv = fd[(size_t)r * NN * CC + (size_t)dst * CC + h * DD + lane];
        float av  = attn[r * HH * DD + h * DD + lane];
        int beg = off[r * (NN + 1) + dst];
        int end = off[r * (NN + 1) + dst + 1];

        float m = -CUDART_INF_F, den = 0.f, acc = 0.f;
        for (int e = beg; e < end; e++) {
            int src = csr_src[r * EE + e];
            float f = fsr[(size_t)src * CC + h * DD + lane];
            float x = f + fdv;
            float lr = (x > 0.f) ? x : 0.2f * x;
            float p = lr * av;
            #pragma unroll
            for (int o = 16; o; o >>= 1)
                p += __shfl_xor_sync(0xFFFFFFFFu, p, o);
            float s = p;
            if (s > m) {
                float c = __expf(m - s);
                den *= c; acc *= c; m = s;
            }
            float w = __expf(s - m);
            den += w;
            acc += w * f;
        }
        if (den > 0.f) total += acc / den;
    }

    if (MEAN) {
        atomicAdd(out + (size_t)dst * DD + lane, 0.25f * total);
    } else {
        out[(size_t)dst * CC + h * DD + lane] = total;
    }
}

// ---------------------------------------------------------------------------
// Launch
// ---------------------------------------------------------------------------
extern "C" void kernel_launch(void* const* d_in, const int* in_sizes, int n_in,
                              void* d_out, int out_size) {
    const float* x    = (const float*)d_in[0];
    const int*   esrc = (const int*)d_in[1];
    const int*   edst = (const int*)d_in[2];
    const float* Wsrc[3], *bsrc[3], *Wdst[3], *bdst[3], *attn[3];
    for (int l = 0; l < 3; l++) {
        Wsrc[l] = (const float*)d_in[3 + 5 * l + 0];
        bsrc[l] = (const float*)d_in[3 + 5 * l + 1];
        Wdst[l] = (const float*)d_in[3 + 5 * l + 2];
        bdst[l] = (const float*)d_in[3 + 5 * l + 3];
        attn[l] = (const float*)d_in[3 + 5 * l + 4];
    }

    void *p_fs, *p_fd, *p_h1, *p_h2, *p_cnt, *p_off, *p_src;
    void *p_ahi, *p_alo, *p_whi, *p_wlo, *p_bias;
    cudaGetSymbolAddress(&p_fs,  g_fs);
    cudaGetSymbolAddress(&p_fd,  g_fd);
    cudaGetSymbolAddress(&p_h1,  g_h1);
    cudaGetSymbolAddress(&p_h2,  g_h2);
    cudaGetSymbolAddress(&p_cnt, g_cnt);
    cudaGetSymbolAddress(&p_off, g_off);
    cudaGetSymbolAddress(&p_src, g_src);
    cudaGetSymbolAddress(&p_ahi, g_ahi);
    cudaGetSymbolAddress(&p_alo, g_alo);
    cudaGetSymbolAddress(&p_whi, g_whi);
    cudaGetSymbolAddress(&p_wlo, g_wlo);
    cudaGetSymbolAddress(&p_bias, g_bias);
    float* fs = (float*)p_fs;  float* fd = (float*)p_fd;
    float* h1 = (float*)p_h1;  float* h2 = (float*)p_h2;
    int* cnt = (int*)p_cnt;    int* off = (int*)p_off;   int* csr_src = (int*)p_src;
    __nv_bfloat16* ahi = (__nv_bfloat16*)p_ahi;
    __nv_bfloat16* alo = (__nv_bfloat16*)p_alo;
    __nv_bfloat16* whi = (__nv_bfloat16*)p_whi;
    __nv_bfloat16* wlo = (__nv_bfloat16*)p_wlo;
    float* bias = (float*)p_bias;

    static int smem_set = 0;
    if (!smem_set) {
        cudaFuncSetAttribute(k_gemm_mma, cudaFuncAttributeMaxDynamicSharedMemorySize,
                             GEMM_SMEM);
        smem_set = 1;
    }

    // --- CSR build ---
    k_zero_cnt<<<(RR * NN + 255) / 256, 256>>>(cnt);
    k_count<<<(RR * EE + 255) / 256, 256>>>(edst, cnt);
    k_scan<<<RR, 1024>>>(cnt, off);
    k_copy_cursor<<<(RR * NN + 255) / 256, 256>>>(off, cnt);
    k_fill<<<(RR * EE + 255) / 256, 256>>>(esrc, edst, cnt, csr_src);

    // --- weight conversion (all layers) ---
    const int WCVT_BLOCKS = (RR * CC * CC + 255) / 256;
    for (int l = 0; l < 3; l++) {
        k_cvt_w<<<WCVT_BLOCKS, 256>>>(Wsrc[l], bsrc[l],
            whi + (size_t)(l * 8 + 0) * CC * CC, wlo + (size_t)(l * 8 + 0) * CC * CC,
            bias + (l * 8 + 0) * CC);
        k_cvt_w<<<WCVT_BLOCKS, 256>>>(Wdst[l], bdst[l],
            whi + (size_t)(l * 8 + 4) * CC * CC, wlo + (size_t)(l * 8 + 4) * CC * CC,
            bias + (l * 8 + 4) * CC);
    }

    const int GEMM_MT = (NN + 127) / 128;   // 391
    const int EDGE_BLOCKS = (NN * HH * 32 + 255) / 256;
    const int XCVT_BLOCKS = (NN * CC / 4 + 255) / 256;

    const float* h = x;
    for (int l = 0; l < 3; l++) {
        k_cvt_x<<<XCVT_BLOCKS, 256>>>(h, ahi, alo);
        k_gemm_mma<<<dim3(GEMM_MT, 8), 256, GEMM_SMEM>>>(
            ahi, alo,
            whi + (size_t)l * 8 * CC * CC, wlo + (size_t)l * 8 * CC * CC,
            bias + l * 8 * CC, fs, fd);
        if (l < 2) {
            float* hn = (l == 0) ? h1 : h2;
            k_edge_agg<false><<<EDGE_BLOCKS, 256>>>(fs, fd, attn[l], off, csr_src, hn);
            h = hn;
        } else {
            cudaMemsetAsync(d_out, 0, (size_t)out_size * sizeof(float), 0);
            k_edge_agg<true><<<EDGE_BLOCKS, 256>>>(fs, fd, attn[l], off, csr_src,
                                                   (float*)d_out);
        }
    }
}

// round 8
// speedup vs baseline: 2.3632x; 1.4748x over previous
#include <cuda_runtime.h>
#include <cuda_bf16.h>
#include <math_constants.h>
#include <cstdint>

// Problem constants
#define NN   50000
#define EE   200000
#define RR   4
#define CC   128
#define HH   4
#define DD   32

// ---------------------------------------------------------------------------
// Device scratch (allocation-free rule: __device__ globals)
// ---------------------------------------------------------------------------
__device__ float g_fs[RR * NN * CC];
__device__ float g_fd[RR * NN * CC];
__device__ int   g_cnt[RR * NN];
__device__ int   g_off[RR * (NN + 1)];
__device__ int   g_src[RR * EE];
__device__ __nv_bfloat16 g_ahi[NN * CC];
__device__ __nv_bfloat16 g_alo[NN * CC];
__device__ __nv_bfloat16 g_whi[3 * 8 * CC * CC];   // [layer][block(8)][n][k]
__device__ __nv_bfloat16 g_wlo[3 * 8 * CC * CC];
__device__ float         g_bias[3 * 8 * CC];

// ---------------------------------------------------------------------------
// CSR construction
// ---------------------------------------------------------------------------
__global__ void k_zero_cnt(int* cnt) {
    int i = blockIdx.x * blockDim.x + threadIdx.x;
    if (i < RR * NN) cnt[i] = 0;
}
__global__ void k_count(const int* __restrict__ edst, int* cnt) {
    int i = blockIdx.x * blockDim.x + threadIdx.x;
    if (i >= RR * EE) return;
    int r = i / EE;
    atomicAdd(&cnt[r * NN + edst[i]], 1);
}
__global__ void k_scan(const int* __restrict__ cnt, int* off) {
    int r = blockIdx.x;
    int t = threadIdx.x;
    const int CH = (NN + 1023) / 1024;
    __shared__ int sums[1024];
    int base = t * CH, s = 0;
    for (int i = 0; i < CH; i++) { int idx = base + i; if (idx < NN) s += cnt[r * NN + idx]; }
    sums[t] = s;
    __syncthreads();
    for (int o = 1; o < 1024; o <<= 1) {
        int v = (t >= o) ? sums[t - o] : 0;
        __syncthreads();
        sums[t] += v;
        __syncthreads();
    }
    int run = (t == 0) ? 0 : sums[t - 1];
    for (int i = 0; i < CH; i++) {
        int idx = base + i;
        if (idx < NN) { off[r * (NN + 1) + idx] = run; run += cnt[r * NN + idx]; }
    }
    if (t == 1023) off[r * (NN + 1) + NN] = run;
}
__global__ void k_copy_cursor(const int* __restrict__ off, int* cur) {
    int i = blockIdx.x * blockDim.x + threadIdx.x;
    if (i >= RR * NN) return;
    int r = i / NN, n = i - r * NN;
    cur[i] = off[r * (NN + 1) + n];
}
__global__ void k_fill(const int* __restrict__ esrc, const int* __restrict__ edst,
                       int* cur, int* csr_src) {
    int i = blockIdx.x * blockDim.x + threadIdx.x;
    if (i >= RR * EE) return;
    int r = i / EE;
    int pos = atomicAdd(&cur[r * NN + edst[i]], 1);
    csr_src[r * EE + pos] = esrc[i];
}

// ---------------------------------------------------------------------------
// fp32 -> bf16 hi/lo split conversions
// ---------------------------------------------------------------------------
__global__ void k_cvt_x(const float* __restrict__ x,
                        __nv_bfloat16* __restrict__ hi, __nv_bfloat16* __restrict__ lo) {
    int i = blockIdx.x * blockDim.x + threadIdx.x;
    if (i >= NN * CC / 4) return;
    float4 v = ((const float4*)x)[i];
    __nv_bfloat16 h0 = __float2bfloat16(v.x), h1 = __float2bfloat16(v.y);
    __nv_bfloat16 h2 = __float2bfloat16(v.z), h3 = __float2bfloat16(v.w);
    __nv_bfloat16 l0 = __float2bfloat16(v.x - __bfloat162float(h0));
    __nv_bfloat16 l1 = __float2bfloat16(v.y - __bfloat162float(h1));
    __nv_bfloat16 l2 = __float2bfloat16(v.z - __bfloat162float(h2));
    __nv_bfloat16 l3 = __float2bfloat16(v.w - __bfloat162float(h3));
    __nv_bfloat162 hp0(h0, h1), hp1(h2, h3), lp0(l0, l1), lp1(l2, l3);
    ((__nv_bfloat162*)hi)[2 * i]     = hp0;
    ((__nv_bfloat162*)hi)[2 * i + 1] = hp1;
    ((__nv_bfloat162*)lo)[2 * i]     = lp0;
    ((__nv_bfloat162*)lo)[2 * i + 1] = lp1;
}

// transpose W[r][k][n] -> out[r][n][k] with hi/lo split; also copy bias
__global__ void k_cvt_w(const float* __restrict__ W, const float* __restrict__ bvec,
                        __nv_bfloat16* __restrict__ w_hi, __nv_bfloat16* __restrict__ w_lo,
                        float* __restrict__ bias_out) {
    int i = blockIdx.x * blockDim.x + threadIdx.x;
    if (i >= RR * CC * CC) return;
    int r   = i / (CC * CC);
    int rem = i - r * (CC * CC);
    int n   = rem / CC;
    int k   = rem - n * CC;
    float w = W[(size_t)r * CC * CC + (size_t)k * CC + n];
    __nv_bfloat16 h = __float2bfloat16(w);
    __nv_bfloat16 l = __float2bfloat16(w - __bfloat162float(h));
    w_hi[i] = h;
    w_lo[i] = l;
    if (k == 0) bias_out[r * CC + n] = bvec[r * CC + n];
}

// ---------------------------------------------------------------------------
// HMMA helpers (portable mma.sync path — tcgen05 unavailable on compute_103)
// ---------------------------------------------------------------------------
__device__ __forceinline__ uint32_t smem_u32(const void* p) {
    uint32_t a;
    asm("{ .reg .u64 t; cvta.to.shared.u64 t, %1; cvt.u32.u64 %0, t; }"
        : "=r"(a) : "l"(p));
    return a;
}
__device__ __forceinline__ void ldsm_x4(uint32_t* r, uint32_t addr) {
    asm volatile("ldmatrix.sync.aligned.m8n8.x4.shared.b16 {%0,%1,%2,%3}, [%4];"
        : "=r"(r[0]), "=r"(r[1]), "=r"(r[2]), "=r"(r[3]) : "r"(addr));
}
#define MMA16816(c, a, b) \
    asm volatile("mma.sync.aligned.m16n8k16.row.col.f32.bf16.bf16.f32 " \
        "{%0,%1,%2,%3}, {%4,%5,%6,%7}, {%8,%9}, {%0,%1,%2,%3};" \
        : "+f"((c)[0]), "+f"((c)[1]), "+f"((c)[2]), "+f"((c)[3]) \
        : "r"((a)[0]), "r"((a)[1]), "r"((a)[2]), "r"((a)[3]), \
          "r"((b)[0]), "r"((b)[1]))

#define TPAD       72
#define TILE_ELEMS (128 * TPAD)
#define GEMM_SMEM  (4 * TILE_ELEMS * 2)   // 73728 B: Ahi, Alo, Bhi, Blo

// ---------------------------------------------------------------------------
// bf16 hi/lo split GEMM via mma.sync (unchanged from R6).
// ---------------------------------------------------------------------------
__global__ __launch_bounds__(256) void k_gemm_mma(
    const __nv_bfloat16* __restrict__ a_hi, const __nv_bfloat16* __restrict__ a_lo,
    const __nv_bfloat16* __restrict__ w_hi, const __nv_bfloat16* __restrict__ w_lo,
    const float* __restrict__ bias,
    float* __restrict__ fs, float* __restrict__ fd) {
    extern __shared__ __align__(16) char dsm[];
    __nv_bfloat16* sAhi = (__nv_bfloat16*)dsm;
    __nv_bfloat16* sAlo = sAhi + TILE_ELEMS;
    __nv_bfloat16* sBhi = sAlo + TILE_ELEMS;
    __nv_bfloat16* sBlo = sBhi + TILE_ELEMS;

    const int tid  = threadIdx.x;
    const int wid  = tid >> 5;
    const int lane = tid & 31;
    const int wm   = wid >> 1;
    const int wn   = wid & 1;
    const int m0   = blockIdx.x * 128;
    const int b    = blockIdx.y;

    const __nv_bfloat16* gAhi = a_hi + (size_t)m0 * CC;
    const __nv_bfloat16* gAlo = a_lo + (size_t)m0 * CC;
    const __nv_bfloat16* gBhi = w_hi + (size_t)b * CC * CC;
    const __nv_bfloat16* gBlo = w_lo + (size_t)b * CC * CC;

    float acc[2][8][4];
    #pragma unroll
    for (int i = 0; i < 2; i++)
        #pragma unroll
        for (int j = 0; j < 8; j++)
            #pragma unroll
            for (int q = 0; q < 4; q++) acc[i][j][q] = 0.f;

    const int sub = lane >> 3;
    const int rin = lane & 7;

    #pragma unroll
    for (int k0 = 0; k0 < 128; k0 += 64) {
        #pragma unroll
        for (int i = 0; i < 4; i++) {
            int idx = tid + i * 256;
            int row = idx >> 3, ch = idx & 7;
            size_t go = (size_t)row * CC + k0 + ch * 8;
            int so = row * TPAD + ch * 8;
            uint4 zv = make_uint4(0u, 0u, 0u, 0u);
            bool okA = (m0 + row) < NN;
            *(uint4*)(sAhi + so) = okA ? *(const uint4*)(gAhi + go) : zv;
            *(uint4*)(sAlo + so) = okA ? *(const uint4*)(gAlo + go) : zv;
            *(uint4*)(sBhi + so) = *(const uint4*)(gBhi + go);
            *(uint4*)(sBlo + so) = *(const uint4*)(gBlo + go);
        }
        __syncthreads();

        #pragma unroll
        for (int kk = 0; kk < 64; kk += 16) {
            uint32_t afh[2][4], afl[2][4], bfh[8][2], bfl[8][2];
            #pragma unroll
            for (int mt = 0; mt < 2; mt++) {
                int ar = wm * 32 + mt * 16 + (sub & 1) * 8 + rin;
                int ac = kk + (sub >> 1) * 8;
                int off = ar * TPAD + ac;
                ldsm_x4(afh[mt], smem_u32(sAhi + off));
                ldsm_x4(afl[mt], smem_u32(sAlo + off));
            }
            #pragma unroll
            for (int nt2 = 0; nt2 < 4; nt2++) {
                int br = wn * 64 + nt2 * 16 + (sub >> 1) * 8 + rin;
                int bc = kk + (sub & 1) * 8;
                int off = br * TPAD + bc;
                uint32_t t[4];
                ldsm_x4(t, smem_u32(sBhi + off));
                bfh[nt2 * 2][0] = t[0]; bfh[nt2 * 2][1] = t[1];
                bfh[nt2 * 2 + 1][0] = t[2]; bfh[nt2 * 2 + 1][1] = t[3];
                ldsm_x4(t, smem_u32(sBlo + off));
                bfl[nt2 * 2][0] = t[0]; bfl[nt2 * 2][1] = t[1];
                bfl[nt2 * 2 + 1][0] = t[2]; bfl[nt2 * 2 + 1][1] = t[3];
            }
            #pragma unroll
            for (int mt = 0; mt < 2; mt++)
                #pragma unroll
                for (int nt = 0; nt < 8; nt++) {
                    MMA16816(acc[mt][nt], afh[mt], bfh[nt]);
                    MMA16816(acc[mt][nt], afh[mt], bfl[nt]);
                    MMA16816(acc[mt][nt], afl[mt], bfh[nt]);
                }
        }
        __syncthreads();
    }

    float* outp = (b < 4) ? (fs + (size_t)b * NN * CC)
                          : (fd + (size_t)(b - 4) * NN * CC);
    const float* bv = bias + b * CC;
    const int qr = lane >> 2, qc = lane & 3;
    #pragma unroll
    for (int mt = 0; mt < 2; mt++) {
        int mA = m0 + wm * 32 + mt * 16 + qr;
        #pragma unroll
        for (int nt = 0; nt < 8; nt++) {
            int n = wn * 64 + nt * 8 + qc * 2;
            float b0 = bv[n], b1 = bv[n + 1];
            if (mA < NN) {
                float2 v0 = make_float2(acc[mt][nt][0] + b0, acc[mt][nt][1] + b1);
                *(float2*)(outp + (size_t)mA * CC + n) = v0;
            }
            if (mA + 8 < NN) {
                float2 v1 = make_float2(acc[mt][nt][2] + b0, acc[mt][nt][3] + b1);
                *(float2*)(outp + (size_t)(mA + 8) * CC + n) = v1;
            }
        }
    }
}

// ---------------------------------------------------------------------------
// Edge aggregation v2: one warp per dst, 4 heads in 8-lane groups.
// Lane g=lane>>3 (head), li=lane&7 owns dims [li*4, li*4+4) via float4.
// Score reduce = 3 intra-group shuffles; branchless online softmax.
// MEAN=false: writes bf16 hi/lo split directly (next GEMM input).
// MEAN=true : cross-group reduce, writes fp32 mean over heads.
// ---------------------------------------------------------------------------
template <bool MEAN>
__global__ __launch_bounds__(256) void k_edge_agg2(
    const float* __restrict__ fs, const float* __restrict__ fd,
    const float* __restrict__ attn,
    const int* __restrict__ off, const int* __restrict__ csr_src,
    __nv_bfloat16* __restrict__ out_hi, __nv_bfloat16* __restrict__ out_lo,
    float* __restrict__ out_f) {
    int dst  = (blockIdx.x * blockDim.x + threadIdx.x) >> 5;
    int lane = threadIdx.x & 31;
    if (dst >= NN) return;
    const int dbase = (lane >> 3) * DD + (lane & 7) * 4;   // dims within 128

    float4 total = make_float4(0.f, 0.f, 0.f, 0.f);
    #pragma unroll
    for (int r = 0; r < RR; r++) {
        const float* fsr = fs + (size_t)r * NN * CC;
        float4 fdv = *(const float4*)(fd + (size_t)r * NN * CC + (size_t)dst * CC + dbase);
        float4 av  = *(const float4*)(attn + r * HH * DD + dbase);
        int beg = off[r * (NN + 1) + dst];
        int end = off[r * (NN + 1) + dst + 1];

        float m = -CUDART_INF_F, den = 0.f;
        float4 acc = make_float4(0.f, 0.f, 0.f, 0.f);
        if (beg < end) {
            const int* sp = csr_src + r * EE;
            float4 fnext = *(const float4*)(fsr + (size_t)sp[beg] * CC + dbase);
            for (int e = beg; e < end; e++) {
                float4 f = fnext;
                if (e + 1 < end)    // prefetch next edge's row
                    fnext = *(const float4*)(fsr + (size_t)sp[e + 1] * CC + dbase);
                float x0 = f.x + fdv.x, x1 = f.y + fdv.y;
                float x2 = f.z + fdv.z, x3 = f.w + fdv.w;
                x0 = (x0 > 0.f) ? x0 : 0.2f * x0;
                x1 = (x1 > 0.f) ? x1 : 0.2f * x1;
                x2 = (x2 > 0.f) ? x2 : 0.2f * x2;
                x3 = (x3 > 0.f) ? x3 : 0.2f * x3;
                float p = x0 * av.x + x1 * av.y + x2 * av.z + x3 * av.w;
                p += __shfl_xor_sync(0xFFFFFFFFu, p, 1);
                p += __shfl_xor_sync(0xFFFFFFFFu, p, 2);
                p += __shfl_xor_sync(0xFFFFFFFFu, p, 4);
                float nm = fmaxf(m, p);
                float c  = __expf(m - nm);    // exp(-inf)=0 on first edge
                float w  = __expf(p - nm);
                m = nm;
                den = den * c + w;
                acc.x = acc.x * c + w * f.x;
                acc.y = acc.y * c + w * f.y;
                acc.z = acc.z * c + w * f.z;
                acc.w = acc.w * c + w * f.w;
            }
            float inv = 1.f / den;
            total.x += acc.x * inv;
            total.y += acc.y * inv;
            total.z += acc.z * inv;
            total.w += acc.w * inv;
        }
    }

    if (MEAN) {
        // sum over the 4 head groups (xor 8, 16), lanes 0..7 write
        #pragma unroll
        for (int o = 8; o <= 16; o <<= 1) {
            total.x += __shfl_xor_sync(0xFFFFFFFFu, total.x, o);
            total.y += __shfl_xor_sync(0xFFFFFFFFu, total.y, o);
            total.z += __shfl_xor_sync(0xFFFFFFFFu, total.z, o);
            total.w += __shfl_xor_sync(0xFFFFFFFFu, total.w, o);
        }
        if (lane < 8) {
            float4 v = make_float4(0.25f * total.x, 0.25f * total.y,
                                   0.25f * total.z, 0.25f * total.w);
            *(float4*)(out_f + (size_t)dst * DD + lane * 4) = v;
        }
    } else {
        // bf16 hi/lo split write (flatten heads): 4 bf16 = 8B per lane
        __nv_bfloat16 h0 = __float2bfloat16(total.x);
        __nv_bfloat16 h1 = __float2bfloat16(total.y);
        __nv_bfloat16 h2 = __float2bfloat16(total.z);
        __nv_bfloat16 h3 = __float2bfloat16(total.w);
        __nv_bfloat162 hp0(h0, h1), hp1(h2, h3);
        __nv_bfloat162 lp0(__float2bfloat16(total.x - __bfloat162float(h0)),
                           __float2bfloat16(total.y - __bfloat162float(h1)));
        __nv_bfloat162 lp1(__float2bfloat16(total.z - __bfloat162float(h2)),
                           __float2bfloat16(total.w - __bfloat162float(h3)));
        size_t o2 = ((size_t)dst * CC + dbase) >> 1;
        ((__nv_bfloat162*)out_hi)[o2]     = hp0;
        ((__nv_bfloat162*)out_hi)[o2 + 1] = hp1;
        ((__nv_bfloat162*)out_lo)[o2]     = lp0;
        ((__nv_bfloat162*)out_lo)[o2 + 1] = lp1;
    }
}

// ---------------------------------------------------------------------------
// Launch
// ---------------------------------------------------------------------------
extern "C" void kernel_launch(void* const* d_in, const int* in_sizes, int n_in,
                              void* d_out, int out_size) {
    const float* x    = (const float*)d_in[0];
    const int*   esrc = (const int*)d_in[1];
    const int*   edst = (const int*)d_in[2];
    const float* Wsrc[3], *bsrc[3], *Wdst[3], *bdst[3], *attn[3];
    for (int l = 0; l < 3; l++) {
        Wsrc[l] = (const float*)d_in[3 + 5 * l + 0];
        bsrc[l] = (const float*)d_in[3 + 5 * l + 1];
        Wdst[l] = (const float*)d_in[3 + 5 * l + 2];
        bdst[l] = (const float*)d_in[3 + 5 * l + 3];
        attn[l] = (const float*)d_in[3 + 5 * l + 4];
    }

    void *p_fs, *p_fd, *p_cnt, *p_off, *p_src;
    void *p_ahi, *p_alo, *p_whi, *p_wlo, *p_bias;
    cudaGetSymbolAddress(&p_fs,  g_fs);
    cudaGetSymbolAddress(&p_fd,  g_fd);
    cudaGetSymbolAddress(&p_cnt, g_cnt);
    cudaGetSymbolAddress(&p_off, g_off);
    cudaGetSymbolAddress(&p_src, g_src);
    cudaGetSymbolAddress(&p_ahi, g_ahi);
    cudaGetSymbolAddress(&p_alo, g_alo);
    cudaGetSymbolAddress(&p_whi, g_whi);
    cudaGetSymbolAddress(&p_wlo, g_wlo);
    cudaGetSymbolAddress(&p_bias, g_bias);
    float* fs = (float*)p_fs;  float* fd = (float*)p_fd;
    int* cnt = (int*)p_cnt;    int* off = (int*)p_off;   int* csr_src = (int*)p_src;
    __nv_bfloat16* ahi = (__nv_bfloat16*)p_ahi;
    __nv_bfloat16* alo = (__nv_bfloat16*)p_alo;
    __nv_bfloat16* whi = (__nv_bfloat16*)p_whi;
    __nv_bfloat16* wlo = (__nv_bfloat16*)p_wlo;
    float* bias = (float*)p_bias;

    static int smem_set = 0;
    if (!smem_set) {
        cudaFuncSetAttribute(k_gemm_mma, cudaFuncAttributeMaxDynamicSharedMemorySize,
                             GEMM_SMEM);
        smem_set = 1;
    }

    // --- CSR build ---
    k_zero_cnt<<<(RR * NN + 255) / 256, 256>>>(cnt);
    k_count<<<(RR * EE + 255) / 256, 256>>>(edst, cnt);
    k_scan<<<RR, 1024>>>(cnt, off);
    k_copy_cursor<<<(RR * NN + 255) / 256, 256>>>(off, cnt);
    k_fill<<<(RR * EE + 255) / 256, 256>>>(esrc, edst, cnt, csr_src);

    // --- weight conversion (all layers) ---
    const int WCVT_BLOCKS = (RR * CC * CC + 255) / 256;
    for (int l = 0; l < 3; l++) {
        k_cvt_w<<<WCVT_BLOCKS, 256>>>(Wsrc[l], bsrc[l],
            whi + (size_t)(l * 8 + 0) * CC * CC, wlo + (size_t)(l * 8 + 0) * CC * CC,
            bias + (l * 8 + 0) * CC);
        k_cvt_w<<<WCVT_BLOCKS, 256>>>(Wdst[l], bdst[l],
            whi + (size_t)(l * 8 + 4) * CC * CC, wlo + (size_t)(l * 8 + 4) * CC * CC,
            bias + (l * 8 + 4) * CC);
    }

    const int GEMM_MT = (NN + 127) / 128;            // 391
    const int EDGE_BLOCKS = (NN * 32 + 255) / 256;   // warp per dst
    const int XCVT_BLOCKS = (NN * CC / 4 + 255) / 256;

    // layer 0 input conversion (only place cvt_x is needed)
    k_cvt_x<<<XCVT_BLOCKS, 256>>>(x, ahi, alo);

    for (int l = 0; l < 3; l++) {
        k_gemm_mma<<<dim3(GEMM_MT, 8), 256, GEMM_SMEM>>>(
            ahi, alo,
            whi + (size_t)l * 8 * CC * CC, wlo + (size_t)l * 8 * CC * CC,
            bias + l * 8 * CC, fs, fd);
        if (l < 2) {
            // write next layer's bf16 hi/lo input directly
            k_edge_agg2<false><<<EDGE_BLOCKS, 256>>>(fs, fd, attn[l], off, csr_src,
                                                     ahi, alo, nullptr);
        } else {
            k_edge_agg2<true><<<EDGE_BLOCKS, 256>>>(fs, fd, attn[l], off, csr_src,
                                                    nullptr, nullptr, (float*)d_out);
        }
    }
}